// round 17
// baseline (speedup 1.0000x reference)
#include <cuda_runtime.h>
#include <cuda_fp16.h>
#include <cstdint>

// ============================================================
// out[b,n] = sum_{c,p} x[b,c,p]*mask[p,c,n]*ro[c,n]
//          = A(256 x 82944) @ W(82944 x 2000),  k = p*64+c
//   A[b,k] = fp16(x[b,c,p])                  (pack kernel)
//   W[k,n] = fp16(mask)*fp16(ro[k&63,n]*1024)  (built on the fly;
//            output scaled by 1/1024)
// R17 = R15 (best: 415us, L1 63.7%, issue 27.2%) + KTILE 32->64:
//   - barriers 288->144 (halves latency exposure, the measured
//     ~113us residual)
//   - mask-LDG refills placed BETWEEN the two MMA k-halves so
//     LDG latency hides under HMMA
//   - KTILE=64 spans all 64 channels once -> no rr parity;
//     regs stay ~128, launch_bounds(256,2) keeps 2 CTAs/SM
//   - SA=72 (LDSM conflict-free), SB=66 (build STS conflict-free,
//     frag lds 2-way as in R15)
// GEMM: mma.sync.m16n8k16 f32-accum, CTA 128m x 128n,
//      warp tile 64m x 32n (2m x 4n), grid 16 x 2 x 9 = 288 CTAs.
// ============================================================

constexpr int BB   = 256;
constexpr int CCH  = 64;
constexpr int PPX  = 1296;
constexpr int NN   = 2000;
constexpr int NPAD = 2048;
constexpr long long KT_TOT = 82944;

constexpr int KSPLIT = 9;
constexpr int KSLICE = 9216;                  // 82944/9
constexpr int KTILE  = 64;
constexpr int NKT    = KSLICE / KTILE;        // 144
constexpr int MTILE  = 128;
constexpr int NTILE  = 128;
constexpr int NTX    = 16;

constexpr int SA = 72;                        // A smem stride (halves), 144B rows
constexpr int SB = 66;                        // B smem stride (halves), 132B rows
constexpr int A_ST = MTILE * SA;              // 9216 halves / stage
constexpr int B_ST = NTILE * SB;              // 8448 halves / stage
constexpr int SM_A_BYTES  = 2 * A_ST * 2;     // 36864
constexpr int SM_B_BYTES  = 2 * B_ST * 2;     // 33792
constexpr int SMEM_TOTAL  = SM_A_BYTES + SM_B_BYTES;  // 70656

// ------------- scratch (device globals; no runtime allocs allowed) ----------
__device__ __half g_Ah[(size_t)BB * KT_TOT];               // 42.5 MB
__device__ float  g_part[(size_t)KSPLIT * BB * NPAD];      // 18.9 MB

// ----------------------------- helpers --------------------------------------
__device__ __forceinline__ uint32_t smem_u32(const void* p) {
    uint32_t a;
    asm("{ .reg .u64 t; cvta.to.shared.u64 t, %1; cvt.u32.u64 %0, t; }"
        : "=r"(a) : "l"(p));
    return a;
}
__device__ __forceinline__ uint32_t lds_u32(uint32_t a) {
    uint32_t v;
    asm volatile("ld.shared.b32 %0, [%1];" : "=r"(v) : "r"(a));
    return v;
}
#define STS_U32(addr, v) \
    asm volatile("st.shared.b32 [%0], %1;" :: "r"(addr), "r"(v) : "memory")
#define CP_A16(dst, src) \
    asm volatile("cp.async.cg.shared.global [%0], [%1], 16;" :: "r"(dst), "l"(src))
#define CP_COMMIT() asm volatile("cp.async.commit_group;" ::: "memory")
#define CP_WAIT0()  asm volatile("cp.async.wait_group 0;" ::: "memory")
#define LDSM4(r0, r1, r2, r3, addr) \
    asm volatile("ldmatrix.sync.aligned.m8n8.x4.shared.b16 {%0,%1,%2,%3}, [%4];" \
        : "=r"(r0), "=r"(r1), "=r"(r2), "=r"(r3) : "r"(addr))
#define MMA16816(d0, d1, d2, d3, a0, a1, a2, a3, b0, b1) \
    asm volatile("mma.sync.aligned.m16n8k16.row.col.f32.f16.f16.f32 " \
        "{%0,%1,%2,%3}, {%4,%5,%6,%7}, {%8,%9}, {%0,%1,%2,%3};" \
        : "+f"(d0), "+f"(d1), "+f"(d2), "+f"(d3) \
        : "r"(a0), "r"(a1), "r"(a2), "r"(a3), "r"(b0), "r"(b1))

// ------------------ dummy kernels (shift ncu capture slot onto gemm) --------
__global__ void warm_a_kernel() {}
__global__ void warm_b_kernel() {}

// ------------------ kernel 1: pack x -> Ah[b][p*64+c] (fp16) ----------------
__global__ void pack_x_kernel(const float* __restrict__ x) {
    __shared__ float s[64][65];
    int b = blockIdx.y;
    int p0 = blockIdx.x * 64;
    int tid = threadIdx.x;
    const float* xb = x + (size_t)b * (CCH * PPX);
    #pragma unroll
    for (int it = 0; it < 16; it++) {
        int t = tid + it * 256;
        int c = t >> 6, i = t & 63, p = p0 + i;
        s[c][i] = (p < PPX) ? xb[c * PPX + p] : 0.f;
    }
    __syncthreads();
    __half* ab = g_Ah + (size_t)b * KT_TOT;
    #pragma unroll
    for (int it = 0; it < 16; it++) {
        int t = tid + it * 256;
        int i = t >> 6, c = t & 63, p = p0 + i;
        if (p < PPX) ab[p * 64 + c] = __float2half_rn(s[c][i]);
    }
}

// ------------------ kernel 2: fused fp16 mma.sync GEMM ----------------------
__global__ void __launch_bounds__(256, 2)
gemm_kernel(const float* __restrict__ mask, const float* __restrict__ ro) {
    extern __shared__ __align__(16) unsigned char smraw[];
    __half* As  = reinterpret_cast<__half*>(smraw);
    __half* Bsm = reinterpret_cast<__half*>(smraw + SM_A_BYTES);

    int tid = threadIdx.x, w = tid >> 5, l = tid & 31;
    int n0 = blockIdx.x * NTILE;
    int m0 = blockIdx.y * MTILE;
    long long kbase = (long long)blockIdx.z * KSLICE;

    // B-build mapping (interleaved): thread (nq, kq) owns n = n0 + nq + 32q,
    // k rows {2kq + 16it + h}, it = 0..3, h = 0..1  (full KTILE=64)
    int nq = tid & 31, kq = (tid >> 5) & 7;
    bool valq[4];
    #pragma unroll
    for (int q = 0; q < 4; q++) valq[q] = (n0 + nq + 32 * q) < NN;

    // readout in registers: rr[it][q] = half2{ro[c0][n], ro[c0+1][n]}*1024,
    // c0 = 2kq + 16it  (KTILE=64 covers all 64 channels once: no parity)
    __half2 rr[4][4];
    #pragma unroll
    for (int it = 0; it < 4; it++) {
        #pragma unroll
        for (int q = 0; q < 4; q++) {
            int n = n0 + nq + 32 * q;
            bool ok = (n < NN);
            int c0 = 2 * kq + 16 * it;
            float a0 = ok ? ro[(size_t)c0 * NN + n] * 1024.f : 0.f;
            float a1 = ok ? ro[(size_t)(c0 + 1) * NN + n] * 1024.f : 0.f;
            rr[it][q] = __floats2half2_rn(a0, a1);
        }
    }

    // A cp.async mapping: 2 threads per row; each copies 64B of the 128B row
    const __half* arow = g_Ah + (size_t)(m0 + (tid >> 1)) * KT_TOT + kbase
                              + (size_t)((tid & 1) * 32);
    uint32_t sbase = smem_u32(As);
    uint32_t adst  = sbase + (uint32_t)((tid >> 1) * (SA * 2) + (tid & 1) * 64);
    uint32_t bbase = smem_u32(Bsm);

    // mrx holds HALF a k-tile of mask values (it = 2h, 2h+1)
    float mrx[16];
    auto ldmaskH = [&](int kt, int h) {
        #pragma unroll
        for (int j = 0; j < 2; j++) {
            int itg = 2 * h + j;
            #pragma unroll
            for (int hh = 0; hh < 2; hh++) {
                long long krow = kbase + (long long)(kt * KTILE + 2 * kq + 16 * itg + hh);
                const float* rowp = mask + krow * NN + n0 + nq;
                #pragma unroll
                for (int q = 0; q < 4; q++)
                    mrx[(j * 2 + hh) * 4 + q] = valq[q] ? rowp[32 * q] : 0.f;
            }
        }
    };

    // build half a B tile (layout [n][k], stride SB=66; lane n-stride 132B
    // = 33 words odd -> conflict-free STS)
    auto buildH = [&](int s, int h) {
        uint32_t bst = bbase + (uint32_t)(s * (B_ST * 2));
        #pragma unroll
        for (int j = 0; j < 2; j++) {
            int itg = 2 * h + j;
            int k0 = 2 * kq + 16 * itg;
            #pragma unroll
            for (int q = 0; q < 4; q++) {
                int nn = nq + 32 * q;
                __half2 mm = __floats2half2_rn(mrx[(j * 2 + 0) * 4 + q],
                                               mrx[(j * 2 + 1) * 4 + q]);
                __half2 hh2 = __hmul2(mm, rr[itg][q]);
                STS_U32(bst + (uint32_t)(nn * (SB * 2)) + (uint32_t)(k0 * 2),
                        *reinterpret_cast<uint32_t*>(&hh2));
            }
        }
    };

    auto cpA = [&](int kt, int s) {
        uint32_t d = adst + (uint32_t)(s * (A_ST * 2));
        const __half* src = arow + (size_t)kt * KTILE;
        #pragma unroll
        for (int c4 = 0; c4 < 4; c4++)
            CP_A16(d + c4 * 16, src + c4 * 8);
    };

    // fragment addressing: warp tile 64(m) x 32(n); 2 m-warps x 4 n-warps
    int wm = (w & 1) * 64, wn = (w >> 1) * 32;
    uint32_t aLdsm = sbase + (uint32_t)(((wm + (l & 15)) * SA + ((l & 16) ? 8 : 0)) * 2);
    uint32_t bfrag0 = bbase + (uint32_t)((wn + (l >> 2)) * SB * 2) + (uint32_t)(4 * (l & 3));

    float acc[4][4][4];
    #pragma unroll
    for (int i = 0; i < 4; i++)
        #pragma unroll
        for (int j = 0; j < 4; j++)
            #pragma unroll
            for (int q = 0; q < 4; q++) acc[i][j][q] = 0.f;

    // one k-half of MMA work: ksh in {0,1} covers ks = 2ksh, 2ksh+1
    auto mmaHalf = [&](uint32_t aS, uint32_t bS, int ksh) {
        #pragma unroll
        for (int ks2 = 0; ks2 < 2; ks2++) {
            int ks = 2 * ksh + ks2;
            uint32_t af[4][4];
            #pragma unroll
            for (int i = 0; i < 4; i++)
                LDSM4(af[i][0], af[i][1], af[i][2], af[i][3],
                      aLdsm * 0 + aS + (uint32_t)(i * 16 * SA * 2) + (uint32_t)(ks * 32));
            #pragma unroll
            for (int j = 0; j < 4; j++) {
                uint32_t ba = bS + (uint32_t)(j * 8 * SB * 2) + (uint32_t)(ks * 32);
                uint32_t b0 = lds_u32(ba);
                uint32_t b1 = lds_u32(ba + 16);
                #pragma unroll
                for (int i = 0; i < 4; i++)
                    MMA16816(acc[i][j][0], acc[i][j][1], acc[i][j][2], acc[i][j][3],
                             af[i][0], af[i][1], af[i][2], af[i][3], b0, b1);
            }
        }
    };

    // ---------------- prologue ---------------------------------------------
    ldmaskH(0, 0);
    cpA(0, 0); CP_COMMIT();
    buildH(0, 0);          // consumes mrx(0, h0)
    ldmaskH(0, 1);
    buildH(0, 1);
    ldmaskH(1, 0);         // leave mrx = (1, h0)

    // ---------------- main loop --------------------------------------------
    for (int kt = 0; kt < NKT; kt++) {
        int s = kt & 1;

        CP_WAIT0();          // A(kt) resident
        __syncthreads();     // publish build(kt) + A(kt); fence prior readers

        uint32_t aS = aLdsm + (uint32_t)(s * (A_ST * 2));
        uint32_t bS = bfrag0 + (uint32_t)(s * (B_ST * 2));
        bool more = (kt + 1 < NKT);

        if (more) {
            cpA(kt + 1, s ^ 1); CP_COMMIT();   // stage read by MMA(kt-1): safe
            buildH(s ^ 1, 0);                  // consumes mrx(kt+1, h0)
            ldmaskH(kt + 1, 1);                // refill; latency hidden by MMA below
        }

        mmaHalf(aS, bS, 0);

        if (more) {
            buildH(s ^ 1, 1);                  // consumes mrx(kt+1, h1)
            if (kt + 2 < NKT) ldmaskH(kt + 2, 0);
        }

        mmaHalf(aS, bS, 1);
    }

    // ---- epilogue: fp32 partials ------------------------------------------
    float* __restrict__ part = g_part + (size_t)blockIdx.z * BB * NPAD;
    int r0 = l >> 2, cq = 2 * (l & 3);
    #pragma unroll
    for (int i = 0; i < 4; i++) {
        #pragma unroll
        for (int j = 0; j < 4; j++) {
            int m = m0 + wm + 16 * i + r0;
            int n = n0 + wn + 8 * j + cq;
            *reinterpret_cast<float2*>(part + (size_t)m * NPAD + n) =
                make_float2(acc[i][j][0], acc[i][j][1]);
            *reinterpret_cast<float2*>(part + (size_t)(m + 8) * NPAD + n) =
                make_float2(acc[i][j][2], acc[i][j][3]);
        }
    }
}

// ------------------ kernel 3: reduce partials -> out (x 1/1024) -------------
__global__ void reduce_kernel(float* __restrict__ out) {
    int id = blockIdx.x * 256 + threadIdx.x;          // id indexes (b, n4)
    int b = id / (NPAD / 4), n4 = id % (NPAD / 4);
    if (b >= BB) return;
    int n = n4 * 4;
    float4 s = make_float4(0.f, 0.f, 0.f, 0.f);
    #pragma unroll
    for (int ks = 0; ks < KSPLIT; ks++) {
        const float4 v = *reinterpret_cast<const float4*>(
            g_part + (size_t)ks * BB * NPAD + (size_t)b * NPAD + n);
        s.x += v.x; s.y += v.y; s.z += v.z; s.w += v.w;
    }
    const float inv = 1.f / 1024.f;
    float* o = out + (size_t)b * NN;
    if (n + 3 < NN) {
        o[n] = s.x * inv; o[n + 1] = s.y * inv; o[n + 2] = s.z * inv; o[n + 3] = s.w * inv;
    } else {
        if (n < NN)     o[n]     = s.x * inv;
        if (n + 1 < NN) o[n + 1] = s.y * inv;
        if (n + 2 < NN) o[n + 2] = s.z * inv;
        if (n + 3 < NN) o[n + 3] = s.w * inv;
    }
}

// ------------------------------- host ---------------------------------------
extern "C" void kernel_launch(void* const* d_in, const int* in_sizes, int n_in,
                              void* d_out, int out_size) {
    const float* x = nullptr;
    const float* mw = nullptr;
    const float* ro = nullptr;
    for (int i = 0; i < n_in; i++) {
        long long sz = in_sizes[i];
        if (sz == (long long)BB * CCH * PPX)      x  = (const float*)d_in[i];
        else if (sz == (long long)PPX * CCH * NN) mw = (const float*)d_in[i];
        else if (sz == (long long)CCH * NN)       ro = (const float*)d_in[i];
    }

    cudaFuncSetAttribute(gemm_kernel, cudaFuncAttributeMaxDynamicSharedMemorySize,
                         SMEM_TOTAL);

    warm_a_kernel<<<1, 32>>>();
    warm_b_kernel<<<1, 32>>>();
    pack_x_kernel<<<dim3(21, BB), 256>>>(x);
    gemm_kernel<<<dim3(NTX, BB / MTILE, KSPLIT), 256, SMEM_TOTAL>>>(mw, ro);
    reduce_kernel<<<(BB * (NPAD / 4) + 255) / 256, 256>>>((float*)d_out);
}